// round 1
// baseline (speedup 1.0000x reference)
#include <cuda_runtime.h>
#include <cuda_bf16.h>
#include <cstdint>

#define BQ   4096      // rows (B*F)
#define DD   256       // feature dim
#define KK   65536     // centroids
#define BM   128       // rows per tile
#define BN   128       // centroids per chunk
#define NCHUNK (KK / BN)         // 512
#define NMTILE (BQ / BM)         // 32
#define CS_STRIDE 132            // padded col stride for centroid smem tile
#define MAIN_GRID 148
#define SMEM_BYTES ((DD * BM + 32 * CS_STRIDE) * 4)   // 147968 bytes

__device__ unsigned long long g_packed[BQ];   // (sortable_dist << 32) | idx
__device__ float              g_csq[KK];      // ||c||^2

__device__ __forceinline__ unsigned fkey(float f) {
    unsigned u = __float_as_uint(f);
    return (u & 0x80000000u) ? ~u : (u | 0x80000000u);
}

// ---------------------------------------------------------------------------
// Kernel: init packed argmin buffer
// ---------------------------------------------------------------------------
__global__ void init_kernel() {
    int i = blockIdx.x * blockDim.x + threadIdx.x;
    if (i < BQ) g_packed[i] = 0xFFFFFFFFFFFFFFFFull;
}

// ---------------------------------------------------------------------------
// Kernel: ||c||^2 per centroid (warp per centroid)
// ---------------------------------------------------------------------------
__global__ void csq_kernel(const float* __restrict__ cent) {
    int warp = threadIdx.x >> 5;
    int lane = threadIdx.x & 31;
    int c = blockIdx.x * 8 + warp;
    const float4* p = (const float4*)(cent + (size_t)c * DD);
    float s = 0.f;
#pragma unroll
    for (int i = 0; i < 2; i++) {
        float4 v = p[lane + 32 * i];
        s = fmaf(v.x, v.x, s);
        s = fmaf(v.y, v.y, s);
        s = fmaf(v.z, v.z, s);
        s = fmaf(v.w, v.w, s);
    }
#pragma unroll
    for (int o = 16; o > 0; o >>= 1) s += __shfl_xor_sync(0xffffffffu, s, o);
    if (lane == 0) g_csq[c] = s;
}

// ---------------------------------------------------------------------------
// Main kernel: fused distance GEMM + running argmin. Persistent CTAs over
// linearized (mtile, chunk) work units.
// ---------------------------------------------------------------------------
__device__ __forceinline__ void flush_best(const float* bestV, const int* bestI,
                                           int mtile, int tx, int ty) {
#pragma unroll
    for (int i = 0; i < 8; i++) {
        unsigned long long p =
            ((unsigned long long)fkey(bestV[i]) << 32) | (unsigned)bestI[i];
#pragma unroll
        for (int o = 1; o < 16; o <<= 1) {
            unsigned long long q = __shfl_xor_sync(0xffffffffu, p, o);
            if (q < p) p = q;
        }
        if (tx == 0) {
            int row = (i < 4) ? (4 * ty + i) : (64 + 4 * ty + (i - 4));
            atomicMin(&g_packed[mtile * BM + row], p);
        }
    }
}

__global__ __launch_bounds__(256, 1)
void main_kernel(const float* __restrict__ x, const float* __restrict__ cent) {
    extern __shared__ float smem[];
    float* xs = smem;                 // [256][128] d-major
    float* cs = smem + DD * BM;       // [32][CS_STRIDE]

    const int tid = threadIdx.x;
    const int tx = tid & 15;
    const int ty = tid >> 4;

    const long total = (long)NMTILE * NCHUNK;      // 16384
    const long s = (long)blockIdx.x * total / gridDim.x;
    const long e = (long)(blockIdx.x + 1) * total / gridDim.x;

    float bestV[8];
    int   bestI[8];
    float acc[8][8];
    int cur_m = -1;

    for (long u = s; u < e; ++u) {
        int mtile = (int)(u >> 9);        // / NCHUNK
        int chunk = (int)(u & 511);       // % NCHUNK

        if (mtile != cur_m) {
            if (cur_m >= 0) flush_best(bestV, bestI, cur_m, tx, ty);
            __syncthreads();
            const float* xg = x + (size_t)mtile * BM * DD;
#pragma unroll 4
            for (int i = 0; i < 32; i++) {
                int idx = i * 256 + tid;
                int row = idx >> 6;
                int dq = (idx & 63) * 4;
                float4 v = *(const float4*)(xg + row * DD + dq);
                xs[(dq + 0) * BM + row] = v.x;
                xs[(dq + 1) * BM + row] = v.y;
                xs[(dq + 2) * BM + row] = v.z;
                xs[(dq + 3) * BM + row] = v.w;
            }
            __syncthreads();
#pragma unroll
            for (int i = 0; i < 8; i++) { bestV[i] = 3.4e38f; bestI[i] = 0; }
            cur_m = mtile;
        }

        const int c0 = chunk * BN;
#pragma unroll
        for (int i = 0; i < 8; i++)
#pragma unroll
            for (int j = 0; j < 8; j++) acc[i][j] = 0.f;

        for (int dk = 0; dk < 8; ++dk) {
            // Prefetch next centroid sub-tile (32 d x 128 cols) into registers
            float4 r[4];
#pragma unroll
            for (int i = 0; i < 4; i++) {
                int idx = i * 256 + tid;
                int col = idx >> 3;
                int dq = (idx & 7) * 4;
                r[i] = *(const float4*)(cent + (size_t)(c0 + col) * DD + dk * 32 + dq);
            }
            __syncthreads();   // previous dk's cs fully consumed
#pragma unroll
            for (int i = 0; i < 4; i++) {
                int idx = i * 256 + tid;
                int col = idx >> 3;
                int dq = (idx & 7) * 4;
                cs[(dq + 0) * CS_STRIDE + col] = r[i].x;
                cs[(dq + 1) * CS_STRIDE + col] = r[i].y;
                cs[(dq + 2) * CS_STRIDE + col] = r[i].z;
                cs[(dq + 3) * CS_STRIDE + col] = r[i].w;
            }
            __syncthreads();

#pragma unroll 8
            for (int d = 0; d < 32; ++d) {
                const float* xrow = xs + (dk * 32 + d) * BM;
                float4 a0 = *(const float4*)(xrow + 4 * ty);
                float4 a1 = *(const float4*)(xrow + 64 + 4 * ty);
                const float* crow = cs + d * CS_STRIDE;
                float4 b0 = *(const float4*)(crow + 4 * tx);
                float4 b1 = *(const float4*)(crow + 64 + 4 * tx);
                float a[8] = {a0.x, a0.y, a0.z, a0.w, a1.x, a1.y, a1.z, a1.w};
                float b[8] = {b0.x, b0.y, b0.z, b0.w, b1.x, b1.y, b1.z, b1.w};
#pragma unroll
                for (int i = 0; i < 8; i++)
#pragma unroll
                    for (int j = 0; j < 8; j++)
                        acc[i][j] = fmaf(a[i], b[j], acc[i][j]);
            }
        }

        // Epilogue: dist = csq - 2*dot, running min (ascending col order -> first-index ties)
        float4 q0 = *(const float4*)(g_csq + c0 + 4 * tx);
        float4 q1 = *(const float4*)(g_csq + c0 + 64 + 4 * tx);
        float q[8] = {q0.x, q0.y, q0.z, q0.w, q1.x, q1.y, q1.z, q1.w};
#pragma unroll
        for (int j = 0; j < 8; j++) {
            int col = c0 + ((j < 4) ? (4 * tx + j) : (64 + 4 * tx + (j - 4)));
#pragma unroll
            for (int i = 0; i < 8; i++) {
                float dist = fmaf(-2.0f, acc[i][j], q[j]);
                if (dist < bestV[i]) { bestV[i] = dist; bestI[i] = col; }
            }
        }
    }
    if (cur_m >= 0) flush_best(bestV, bestI, cur_m, tx, ty);
}

// ---------------------------------------------------------------------------
// Finalize: decode winners, gather centroid rows, write codes (as float)
// ---------------------------------------------------------------------------
__global__ void finalize_kernel(const float* __restrict__ cent,
                                float* __restrict__ out_xhat,
                                float* __restrict__ out_codes) {
    int warp = threadIdx.x >> 5;
    int lane = threadIdx.x & 31;
    int row = blockIdx.x * 8 + warp;
    if (row >= BQ) return;
    unsigned long long p = g_packed[row];
    unsigned idx = (unsigned)(p & 0xFFFFFFFFull);
    if (out_xhat) {
        const float4* src = (const float4*)(cent + (size_t)idx * DD);
        float4* dst = (float4*)(out_xhat + (size_t)row * DD);
        dst[lane] = src[lane];
        dst[lane + 32] = src[lane + 32];
    }
    if (out_codes && lane == 0) out_codes[row] = (float)idx;
}

// ---------------------------------------------------------------------------
extern "C" void kernel_launch(void* const* d_in, const int* in_sizes, int n_in,
                              void* d_out, int out_size) {
    // inputs: [0]=xhat_BFD (unused), [1]=x_BD, [2]=centroids
    const float* x = (const float*)d_in[1];
    const float* cent = (const float*)d_in[2];

    float* out = (float*)d_out;
    float* out_xhat = nullptr;
    float* out_codes = nullptr;
    const int XH = BQ * DD;
    if (out_size >= XH) {
        out_xhat = out;
        if (out_size >= XH + BQ) out_codes = out + XH;
    } else if (out_size >= BQ) {
        out_codes = out;
    }

    cudaFuncSetAttribute(main_kernel,
                         cudaFuncAttributeMaxDynamicSharedMemorySize, SMEM_BYTES);

    init_kernel<<<(BQ + 255) / 256, 256>>>();
    csq_kernel<<<KK / 8, 256>>>(cent);
    main_kernel<<<MAIN_GRID, 256, SMEM_BYTES>>>(x, cent);
    finalize_kernel<<<BQ / 8, 256>>>(cent, out_xhat, out_codes);
}

// round 3
// speedup vs baseline: 2.1403x; 2.1403x over previous
#include <cuda_runtime.h>
#include <cuda_bf16.h>
#include <cstdint>

#define BQ 4096
#define DD 256
#define KK 65536
#define TM 128
#define TN 128
#define NCHUNK 512          // KK / TN
#define NMTILE 32           // BQ / TM
#define MAIN_GRID 148
#define NTHREADS 256
#define MARGIN 1.0f
#define CAND_CAP (1u << 22)

#define APITCH 264                      // padded row pitch in bf16 (528 B)
#define ABYTES (128 * APITCH * 2)       // 67584
#define SM_A   0
#define SM_B0  ABYTES
#define SM_B1  (2 * ABYTES)
#define SMEM_TOTAL (3 * ABYTES)         // 202752 bytes

__device__ __nv_bfloat16 g_cent16[(size_t)KK * DD];   // 32 MB
__device__ __nv_bfloat16 g_x16[(size_t)BQ * DD];      // 2 MB
__device__ float              g_csq[KK];
__device__ unsigned long long g_packed[BQ];           // approx best (fkey<<32)|idx
__device__ unsigned long long g_final[BQ];            // exact best among candidates
__device__ unsigned           g_ncand;
__device__ unsigned           g_cand[CAND_CAP];       // (row<<16)|col

__device__ __forceinline__ unsigned fkey(float f) {
    unsigned u = __float_as_uint(f);
    return (u & 0x80000000u) ? ~u : (u | 0x80000000u);
}
__device__ __forceinline__ float unfkey(unsigned k) {
    unsigned u = (k & 0x80000000u) ? (k ^ 0x80000000u) : ~k;
    return __uint_as_float(u);
}
__device__ __forceinline__ unsigned smem_u32(const void* p) {
    unsigned a;
    asm("{ .reg .u64 t; cvta.to.shared.u64 t, %1; cvt.u32.u64 %0, t; }"
        : "=r"(a) : "l"(p));
    return a;
}
__device__ __forceinline__ void ldsm_x4(unsigned* r, unsigned addr) {
    asm volatile("ldmatrix.sync.aligned.m8n8.x4.shared.b16 {%0,%1,%2,%3},[%4];"
                 : "=r"(r[0]), "=r"(r[1]), "=r"(r[2]), "=r"(r[3]) : "r"(addr));
}
__device__ __forceinline__ void mma_bf16(float* c, const unsigned* a,
                                         const unsigned* b) {
    asm volatile(
        "mma.sync.aligned.m16n8k16.row.col.f32.bf16.bf16.f32 "
        "{%0,%1,%2,%3},{%4,%5,%6,%7},{%8,%9},{%0,%1,%2,%3};"
        : "+f"(c[0]), "+f"(c[1]), "+f"(c[2]), "+f"(c[3])
        : "r"(a[0]), "r"(a[1]), "r"(a[2]), "r"(a[3]), "r"(b[0]), "r"(b[1]));
}

// ---------------------------------------------------------------------------
__global__ void init_kernel() {
    int i = blockIdx.x * blockDim.x + threadIdx.x;
    if (i < BQ) {
        g_packed[i] = 0xFFFFFFFFFFFFFFFFull;
        g_final[i]  = 0xFFFFFFFFFFFFFFFFull;
    }
    if (i == 0) g_ncand = 0u;
}

__global__ void csq_kernel(const float* __restrict__ cent) {
    int warp = threadIdx.x >> 5, lane = threadIdx.x & 31;
    int c = blockIdx.x * 8 + warp;
    const float4* p = (const float4*)(cent + (size_t)c * DD);
    float s = 0.f;
#pragma unroll
    for (int i = 0; i < 2; i++) {
        float4 v = p[lane + 32 * i];
        s = fmaf(v.x, v.x, s); s = fmaf(v.y, v.y, s);
        s = fmaf(v.z, v.z, s); s = fmaf(v.w, v.w, s);
    }
#pragma unroll
    for (int o = 16; o > 0; o >>= 1) s += __shfl_xor_sync(0xffffffffu, s, o);
    if (lane == 0) g_csq[c] = s;
}

__global__ void cvt_cent_kernel(const float* __restrict__ cent) {
    size_t i = (size_t)blockIdx.x * blockDim.x + threadIdx.x;  // float4 units
    float4 v = ((const float4*)cent)[i];
    ((__nv_bfloat162*)g_cent16)[2 * i]     = __floats2bfloat162_rn(v.x, v.y);
    ((__nv_bfloat162*)g_cent16)[2 * i + 1] = __floats2bfloat162_rn(v.z, v.w);
}
__global__ void cvt_x_kernel(const float* __restrict__ x) {
    size_t i = (size_t)blockIdx.x * blockDim.x + threadIdx.x;
    float4 v = ((const float4*)x)[i];
    ((__nv_bfloat162*)g_x16)[2 * i]     = __floats2bfloat162_rn(v.x, v.y);
    ((__nv_bfloat162*)g_x16)[2 * i + 1] = __floats2bfloat162_rn(v.z, v.w);
}

// ---------------------------------------------------------------------------
__device__ __forceinline__ void load_B_async(unsigned bb, int chunk, int tid) {
    const char* src = (const char*)(g_cent16 + (size_t)chunk * TN * DD);
#pragma unroll
    for (int i = 0; i < 16; i++) {
        int j = i * NTHREADS + tid;
        int col = j >> 5, seg = j & 31;
        unsigned dst = bb + (unsigned)col * 528u + (unsigned)seg * 16u;
        const void* gp = src + (size_t)col * 512 + seg * 16;
        asm volatile("cp.async.cg.shared.global [%0], [%1], 16;"
                     :: "r"(dst), "l"(gp));
    }
}

__device__ __forceinline__ void load_A(char* smem, int mtile, int tid) {
    const char* src = (const char*)(g_x16 + (size_t)mtile * TM * DD);
#pragma unroll
    for (int i = 0; i < 16; i++) {
        int j = i * NTHREADS + tid;
        int row = j >> 5, seg = j & 31;
        uint4 v = *(const uint4*)(src + (size_t)row * 512 + seg * 16);
        *(uint4*)(smem + SM_A + row * 528 + seg * 16) = v;
    }
}

__device__ __forceinline__ void flush_best(const float* bestV, const int* bestI,
                                           int rowBase, int lane) {
#pragma unroll
    for (int r = 0; r < 4; r++) {
        unsigned long long p =
            ((unsigned long long)fkey(bestV[r]) << 32) | (unsigned)bestI[r];
        unsigned long long q;
        q = __shfl_xor_sync(0xffffffffu, p, 1); if (q < p) p = q;
        q = __shfl_xor_sync(0xffffffffu, p, 2); if (q < p) p = q;
        if ((lane & 3) == 0) {
            int row = rowBase + (r >> 1) * 16 + (r & 1) * 8 + (lane >> 2);
            atomicMin(&g_packed[row], p);
        }
    }
}

__global__ void __launch_bounds__(NTHREADS, 1) main_kernel() {
    extern __shared__ char smem[];
    const unsigned sbase = smem_u32(smem);
    const int tid = threadIdx.x;
    const int wid = tid >> 5, lane = tid & 31;
    const int wr = wid >> 1, wc = wid & 1;   // warp 32x64 tile at (wr*32, wc*64)

    const long total = (long)NMTILE * NCHUNK;
    const long s = (long)blockIdx.x * total / MAIN_GRID;
    const long e = (long)(blockIdx.x + 1) * total / MAIN_GRID;
    const int T = (int)(e - s);

    // per-thread ldmatrix base addresses (k=0)
    unsigned aAddr[2], bAddrOfs[4];
#pragma unroll
    for (int mi = 0; mi < 2; mi++)
        aAddr[mi] = sbase + SM_A +
                    (unsigned)((wr * 32 + mi * 16 + (lane & 15)) * 528 +
                               ((lane >> 4) * 8) * 2);
#pragma unroll
    for (int nb = 0; nb < 4; nb++)
        bAddrOfs[nb] =
            (unsigned)((wc * 64 + nb * 16 + ((lane >> 4) << 3) + (lane & 7)) * 528 +
                       (((lane >> 3) & 1) * 8) * 2);

    float bestV[4];
    int   bestI[4];
#pragma unroll
    for (int r = 0; r < 4; r++) { bestV[r] = 3.4e38f; bestI[r] = 0; }

    int cur_m = (int)(s >> 9);
    load_A(smem, cur_m, tid);
    load_B_async(sbase + SM_B0, (int)(s & 511), tid);
    asm volatile("cp.async.commit_group;" ::: "memory");

    for (int i = 0; i < T; i++) {
        const long u = s + i;
        const int mt = (int)(u >> 9);
        const int chunk = (int)(u & 511);
        const unsigned bbase = sbase + (unsigned)((i & 1) ? SM_B1 : SM_B0);

        __syncthreads();   // everyone done with A and the buffer we now overwrite
        if (mt != cur_m) {
            flush_best(bestV, bestI, cur_m * TM + wr * 32, lane);
#pragma unroll
            for (int r = 0; r < 4; r++) { bestV[r] = 3.4e38f; bestI[r] = 0; }
            load_A(smem, mt, tid);
            cur_m = mt;
        }
        if (i + 1 < T) {
            load_B_async(sbase + (unsigned)(((i + 1) & 1) ? SM_B1 : SM_B0),
                         (int)((u + 1) & 511), tid);
            asm volatile("cp.async.commit_group;" ::: "memory");
            asm volatile("cp.async.wait_group 1;" ::: "memory");
        } else {
            asm volatile("cp.async.wait_group 0;" ::: "memory");
        }
        __syncthreads();   // B(i) visible to all

        // ---- GEMM: 128x128x256 tile, warp 32x64, acc fp32 ----
        float acc[2][8][4];
#pragma unroll
        for (int mi = 0; mi < 2; mi++)
#pragma unroll
            for (int nf = 0; nf < 8; nf++)
#pragma unroll
                for (int c = 0; c < 4; c++) acc[mi][nf][c] = 0.f;

#pragma unroll
        for (int k16 = 0; k16 < 16; k16++) {
            unsigned a[2][4], b[4][4];
#pragma unroll
            for (int mi = 0; mi < 2; mi++)
                ldsm_x4(a[mi], aAddr[mi] + (unsigned)(k16 * 32));
#pragma unroll
            for (int nb = 0; nb < 4; nb++)
                ldsm_x4(b[nb], bbase + bAddrOfs[nb] + (unsigned)(k16 * 32));
#pragma unroll
            for (int mi = 0; mi < 2; mi++)
#pragma unroll
                for (int nb = 0; nb < 4; nb++) {
                    mma_bf16(acc[mi][nb * 2],     a[mi], &b[nb][0]);
                    mma_bf16(acc[mi][nb * 2 + 1], a[mi], &b[nb][2]);
                }
        }

        // ---- epilogue: dist, running argmin, margin capture ----
        const int col0 = chunk * TN + wc * 64 + 2 * (lane & 3);
        float q[8][2];
#pragma unroll
        for (int nf = 0; nf < 8; nf++) {
            q[nf][0] = __ldg(&g_csq[col0 + nf * 8]);
            q[nf][1] = __ldg(&g_csq[col0 + nf * 8 + 1]);
        }
#pragma unroll
        for (int mi = 0; mi < 2; mi++)
#pragma unroll
            for (int half = 0; half < 2; half++) {
                const int rIdx = mi * 2 + half;
                const int row_g = mt * TM + wr * 32 + mi * 16 + half * 8 + (lane >> 2);
                unsigned long long snap = g_packed[row_g];
                unsigned sk = (unsigned)(snap >> 32);
                float bound = fminf(
                    (sk == 0xFFFFFFFFu) ? 3.4e38f : unfkey(sk),
                    bestV[rIdx]) + MARGIN;
                float bv = bestV[rIdx];
                int   bi = bestI[rIdx];
#pragma unroll
                for (int nf = 0; nf < 8; nf++)
#pragma unroll
                    for (int cc = 0; cc < 2; cc++) {
                        float dist = fmaf(-2.0f, acc[mi][nf][half * 2 + cc],
                                          q[nf][cc]);
                        int col = col0 + nf * 8 + cc;
                        if (dist <= bound) {
                            unsigned slot = atomicAdd(&g_ncand, 1u);
                            if (slot < CAND_CAP)
                                g_cand[slot] = ((unsigned)row_g << 16) |
                                               (unsigned)col;
                        }
                        bound = fminf(bound, dist + MARGIN);
                        if (dist < bv) { bv = dist; bi = col; }
                    }
                bestV[rIdx] = bv;
                bestI[rIdx] = bi;
            }
    }
    flush_best(bestV, bestI, cur_m * TM + wr * 32, lane);
}

// ---------------------------------------------------------------------------
// Exact fp32 rescore of captured candidates
// ---------------------------------------------------------------------------
__global__ void rescore_kernel(const float* __restrict__ x,
                               const float* __restrict__ cent) {
    unsigned n = g_ncand;
    if (n > CAND_CAP) n = CAND_CAP;
    int gw = (blockIdx.x * blockDim.x + threadIdx.x) >> 5;
    int lane = threadIdx.x & 31;
    int nw = (gridDim.x * blockDim.x) >> 5;
    for (unsigned eidx = gw; eidx < n; eidx += nw) {
        unsigned ent = g_cand[eidx];
        unsigned row = ent >> 16;
        unsigned col = ent & 0xFFFFu;
        const float4* xp = (const float4*)(x + (size_t)row * DD);
        const float4* cp = (const float4*)(cent + (size_t)col * DD);
        float sdot = 0.f;
#pragma unroll
        for (int i = 0; i < 2; i++) {
            float4 a = xp[lane + 32 * i];
            float4 b = cp[lane + 32 * i];
            sdot = fmaf(a.x, b.x, sdot); sdot = fmaf(a.y, b.y, sdot);
            sdot = fmaf(a.z, b.z, sdot); sdot = fmaf(a.w, b.w, sdot);
        }
#pragma unroll
        for (int o = 16; o > 0; o >>= 1)
            sdot += __shfl_xor_sync(0xffffffffu, sdot, o);
        if (lane == 0) {
            float dist = fmaf(-2.0f, sdot, __ldg(&g_csq[col]));
            atomicMin(&g_final[row],
                      ((unsigned long long)fkey(dist) << 32) | col);
        }
    }
}

// ---------------------------------------------------------------------------
__global__ void finalize_kernel(const float* __restrict__ cent,
                                float* __restrict__ out_xhat,
                                float* __restrict__ out_codes) {
    int warp = threadIdx.x >> 5, lane = threadIdx.x & 31;
    int row = blockIdx.x * 8 + warp;
    if (row >= BQ) return;
    unsigned idx = (unsigned)(g_final[row] & 0xFFFFFFFFull);
    if (out_xhat) {
        const float4* src = (const float4*)(cent + (size_t)idx * DD);
        float4* dst = (float4*)(out_xhat + (size_t)row * DD);
        dst[lane] = src[lane];
        dst[lane + 32] = src[lane + 32];
    }
    if (out_codes && lane == 0) out_codes[row] = (float)idx;
}

// ---------------------------------------------------------------------------
extern "C" void kernel_launch(void* const* d_in, const int* in_sizes, int n_in,
                              void* d_out, int out_size) {
    const float* x = (const float*)d_in[1];
    const float* cent = (const float*)d_in[2];

    float* out = (float*)d_out;
    float* out_xhat = nullptr;
    float* out_codes = nullptr;
    const int XH = BQ * DD;
    if (out_size >= XH) {
        out_xhat = out;
        if (out_size >= XH + BQ) out_codes = out + XH;
    } else if (out_size >= BQ) {
        out_codes = out;
    }

    cudaFuncSetAttribute(main_kernel,
                         cudaFuncAttributeMaxDynamicSharedMemorySize, SMEM_TOTAL);

    init_kernel<<<(BQ + 255) / 256, 256>>>();
    csq_kernel<<<KK / 8, 256>>>(cent);
    cvt_cent_kernel<<<(KK * DD / 4) / 256, 256>>>(cent);
    cvt_x_kernel<<<(BQ * DD / 4) / 256, 256>>>(x);
    main_kernel<<<MAIN_GRID, NTHREADS, SMEM_TOTAL>>>();
    rescore_kernel<<<512, 256>>>(x, cent);
    finalize_kernel<<<BQ / 8, 256>>>(cent, out_xhat, out_codes);
}